// round 11
// baseline (speedup 1.0000x reference)
#include <cuda_runtime.h>

#define HH 256
#define WW 256
#define BATCH 8
#define CH 64
#define NPIX 65536
#define NTOT (BATCH*CH*NPIX)

// Scratch (static __device__ arrays per harness rules)
__device__ float g_y[NTOT];              // conv output (pre-BN), 128 MB
__device__ float g_wre[CH*3*CH*3];       // reordered weights [ci][kr][co][kc]
__device__ float g_stats[2*CH];          // per-channel sum, sumsq
__device__ float g_ccF[25];              // flipped composed 5x5 (fx*fx + fy*fy)
__device__ float g_fxF[9];               // flipped 3x3 filters
__device__ float g_fyF[9];

// ---------------------------------------------------------------------------
// Prep 1: reorder conv weights OIHW -> [ci][kr][co][kc], zero stats
// ---------------------------------------------------------------------------
__global__ void prep_reorder(const float* __restrict__ w) {
    int idx = blockIdx.x * 256 + threadIdx.x;
    if (idx < 2*CH) g_stats[idx] = 0.f;
    if (idx < CH*CH*9) {
        int kc = idx % 3;
        int t  = idx / 3;
        int co = t % CH;
        int t2 = t / CH;
        int kr = t2 % 3;
        int ci = t2 / 3;
        g_wre[idx] = w[((co*CH + ci)*3 + kr)*3 + kc];
    }
}

// ---------------------------------------------------------------------------
// Prep 2: compose curvature filters.
//   cc = linear_conv(fx,fx) + linear_conv(fy,fy)  (5x5), stored flipped so the
//   curvature kernel can use a sliding-window correlation form.
// ---------------------------------------------------------------------------
__global__ void prep_filters(const float* __restrict__ fx, const float* __restrict__ fy) {
    int t = threadIdx.x;
    if (t < 25) {
        int u = t / 5, v = t - 5*(t/5);
        float s = 0.f;
        for (int a = 0; a < 3; a++)
            for (int b = 0; b < 3; b++) {
                int a2 = u - a, b2 = v - b;
                if (a2 >= 0 && a2 < 3 && b2 >= 0 && b2 < 3)
                    s += fx[a*3+b]*fx[a2*3+b2] + fy[a*3+b]*fy[a2*3+b2];
            }
        g_ccF[24 - t] = s;
    } else if (t < 34) {
        int i = t - 25;
        g_fxF[8 - i] = fx[i];
        g_fyF[8 - i] = fy[i];
    }
}

// ---------------------------------------------------------------------------
// Conv 3x3 (pad 1) + bias, fused per-channel sum/sumsq reduction.
// Block: 256 threads, tile 64(W) x 32(H), 4 output channels (one co-group).
// Thread: 8 consecutive W pixels x 4 co.  Weights for the co-group cached in
// smem once; x tile (66x34, stride-67 for conflict-free LDS) reloaded per ci.
// ---------------------------------------------------------------------------
__global__ __launch_bounds__(256) void conv_kernel(
    const float* __restrict__ xin, const float* __restrict__ bias)
{
    __shared__ float s_tile[34*67];
    __shared__ float s_w[64*36];

    int tid = threadIdx.x;
    int bz  = blockIdx.z;
    int cg  = bz & 15;       // co group (4 channels)
    int b   = bz >> 4;       // batch
    int tileW0 = blockIdx.x << 6;
    int tileH0 = blockIdx.y << 5;
    int h0 = tileH0 - 1, w0 = tileW0 - 1;

    // preload this co-group's weights: s_w[ci*36 + kr*12 + co*3 + kc]
    for (int idx = tid; idx < 64*36; idx += 256) {
        int ci  = idx / 36;
        int rem = idx - ci*36;
        int kr  = rem / 12;
        int r2  = rem - kr*12;
        s_w[idx] = g_wre[(ci*3 + kr)*192 + cg*12 + r2];
    }

    int row  = tid >> 3;          // 0..31
    int colg = (tid & 7) << 3;    // 0,8,..,56

    float acc[4][8];
    #pragma unroll
    for (int co = 0; co < 4; co++)
        #pragma unroll
        for (int p = 0; p < 8; p++) acc[co][p] = 0.f;

    const float* xb = xin + (size_t)b * (CH*NPIX);

    for (int ci = 0; ci < 64; ci++) {
        const float* src = xb + ci*NPIX;
        __syncthreads();   // protects s_tile reuse (and s_w on first iter)
        for (int idx = tid; idx < 34*66; idx += 256) {
            int r  = idx / 66;
            int c2 = idx - r*66;
            int gh = h0 + r, gw = w0 + c2;
            float v = 0.f;
            if ((unsigned)gh < 256u && (unsigned)gw < 256u)
                v = src[(gh << 8) + gw];
            s_tile[r*67 + c2] = v;
        }
        __syncthreads();

        const float* wci = &s_w[ci*36];
        #pragma unroll
        for (int kr = 0; kr < 3; kr++) {
            const float* xr = &s_tile[(row + kr)*67 + colg];
            float xv[10];
            #pragma unroll
            for (int j = 0; j < 10; j++) xv[j] = xr[j];
            #pragma unroll
            for (int co = 0; co < 4; co++) {
                float wa = wci[kr*12 + co*3 + 0];
                float wb = wci[kr*12 + co*3 + 1];
                float wc = wci[kr*12 + co*3 + 2];
                #pragma unroll
                for (int p = 0; p < 8; p++)
                    acc[co][p] += wa*xv[p] + wb*xv[p+1] + wc*xv[p+2];
            }
        }
    }

    // epilogue: bias, store y, per-channel partial sums
    int gh   = tileH0 + row;
    int lane = tid & 31;
    int co0  = cg << 2;
    float red[8];
    #pragma unroll
    for (int co = 0; co < 4; co++) {
        float bv = bias[co0 + co];
        float s = 0.f, q = 0.f;
        float vv[8];
        #pragma unroll
        for (int p = 0; p < 8; p++) {
            float v = acc[co][p] + bv;
            vv[p] = v; s += v; q += v*v;
        }
        float* dst = &g_y[(((b << 6) + co0 + co) << 16) + (gh << 8) + tileW0 + colg];
        ((float4*)dst)[0] = make_float4(vv[0], vv[1], vv[2], vv[3]);
        ((float4*)dst)[1] = make_float4(vv[4], vv[5], vv[6], vv[7]);
        red[co*2] = s; red[co*2+1] = q;
    }
    #pragma unroll
    for (int o = 16; o > 0; o >>= 1)
        #pragma unroll
        for (int k = 0; k < 8; k++)
            red[k] += __shfl_xor_sync(0xffffffffu, red[k], o);
    if (lane == 0) {
        #pragma unroll
        for (int co = 0; co < 4; co++) {
            atomicAdd(&g_stats[co0 + co],      red[co*2]);
            atomicAdd(&g_stats[64 + co0 + co], red[co*2+1]);
        }
    }
}

// ---------------------------------------------------------------------------
// Fused BN(batch stats) + ReLU + circular-conv curvature.
//   x   = relu(bn(y))
//   out = circconv5(x, cc) + (circconv3(x,fx) - circconv3(x,fy))^2 + x
// Block: 256 threads, tile 64(W) x 16(H), one (b,c). Thread: 4 px in a row.
// Smem tile 20x68 (4-wide circular halo, stride 69).
// ---------------------------------------------------------------------------
__global__ __launch_bounds__(256) void curv_kernel(
    const float* __restrict__ gamma, const float* __restrict__ beta,
    float* __restrict__ out)
{
    __shared__ float tile[20*69];
    int tid = threadIdx.x;
    int bz  = blockIdx.z;            // b*64 + c
    int c   = bz & 63;
    int h0  = blockIdx.y << 4;
    int w0  = blockIdx.x << 6;

    const float inv_n = 1.f / 524288.f;
    float mean  = g_stats[c] * inv_n;
    float var   = g_stats[64 + c] * inv_n - mean*mean;
    float scale = gamma[c] * rsqrtf(var + 1e-5f);
    float shift = beta[c] - mean*scale;

    const float* yc = g_y + ((size_t)bz << 16);
    for (int idx = tid; idx < 20*68; idx += 256) {
        int r  = idx / 68;
        int c2 = idx - r*68;
        int gh = (h0 + r - 4) & 255;
        int gw = (w0 + c2 - 4) & 255;
        float v = fmaf(yc[(gh << 8) + gw], scale, shift);
        tile[r*69 + c2] = fmaxf(v, 0.f);
    }

    float ccf[25], fxf[9], fyf[9];
    #pragma unroll
    for (int i = 0; i < 25; i++) ccf[i] = g_ccF[i];
    #pragma unroll
    for (int i = 0; i < 9; i++) { fxf[i] = g_fxF[i]; fyf[i] = g_fyF[i]; }
    __syncthreads();

    int tr = tid >> 4;            // 0..15
    int tc = (tid & 15) << 2;     // 0,4,..,60

    float s5[4] = {0,0,0,0};
    float gx[4] = {0,0,0,0};
    float gy[4] = {0,0,0,0};
    float xc[4] = {0,0,0,0};

    #pragma unroll
    for (int r = 0; r < 5; r++) {
        float xv[8];
        const float* rp = &tile[(tr + r)*69 + tc];
        #pragma unroll
        for (int j = 0; j < 8; j++) xv[j] = rp[j];
        #pragma unroll
        for (int u = 0; u < 5; u++) {
            float wv = ccf[r*5 + u];
            #pragma unroll
            for (int p = 0; p < 4; p++) s5[p] = fmaf(wv, xv[p+u], s5[p]);
        }
        if (r >= 2) {
            int r2 = r - 2;
            #pragma unroll
            for (int u2 = 0; u2 < 3; u2++) {
                float wx = fxf[r2*3 + u2];
                float wy = fyf[r2*3 + u2];
                #pragma unroll
                for (int p = 0; p < 4; p++) {
                    gx[p] = fmaf(wx, xv[p+u2+2], gx[p]);
                    gy[p] = fmaf(wy, xv[p+u2+2], gy[p]);
                }
            }
        }
        if (r == 4) {
            #pragma unroll
            for (int p = 0; p < 4; p++) xc[p] = xv[p+4];
        }
    }

    float4 o;
    float d0 = gx[0]-gy[0], d1 = gx[1]-gy[1], d2 = gx[2]-gy[2], d3 = gx[3]-gy[3];
    o.x = s5[0] + d0*d0 + xc[0];
    o.y = s5[1] + d1*d1 + xc[1];
    o.z = s5[2] + d2*d2 + xc[2];
    o.w = s5[3] + d3*d3 + xc[3];
    float* dst = &out[((size_t)bz << 16) + ((h0 + tr) << 8) + w0 + tc];
    *(float4*)dst = o;
}

// ---------------------------------------------------------------------------
extern "C" void kernel_launch(void* const* d_in, const int* in_sizes, int n_in,
                              void* d_out, int out_size)
{
    const float* feature_map = (const float*)d_in[0];
    const float* conv_w      = (const float*)d_in[1];
    const float* conv_b      = (const float*)d_in[2];
    const float* bn_gamma    = (const float*)d_in[3];
    const float* bn_beta     = (const float*)d_in[4];
    const float* filt_x      = (const float*)d_in[5];
    const float* filt_y      = (const float*)d_in[6];
    float* out = (float*)d_out;

    prep_reorder<<<144, 256>>>(conv_w);
    prep_filters<<<1, 64>>>(filt_x, filt_y);
    conv_kernel<<<dim3(4, 8, 128), 256>>>(feature_map, conv_b);
    curv_kernel<<<dim3(4, 16, 512), 256>>>(bn_gamma, bn_beta, out);
}

// round 12
// speedup vs baseline: 1.0046x; 1.0046x over previous
#include <cuda_runtime.h>

#define HH 256
#define WW 256
#define BATCH 8
#define CH 64
#define NPIX 65536
#define NTOT (BATCH*CH*NPIX)

// Scratch (static __device__ arrays per harness rules)
__device__ float g_y[NTOT];              // conv output (pre-BN), 128 MB
__device__ float g_wre[CH*3*CH*3];       // reordered weights [ci][kr][co][kc]
__device__ float g_stats[2*CH];          // per-channel sum, sumsq
__device__ float g_ccF[25];              // flipped composed 5x5 (fx*fx + fy*fy)
__device__ float g_fxF[9];               // flipped 3x3 filters
__device__ float g_fyF[9];

// ---------------------------------------------------------------------------
// Prep 1: reorder conv weights OIHW -> [ci][kr][co][kc], zero stats
// ---------------------------------------------------------------------------
__global__ void prep_reorder(const float* __restrict__ w) {
    int idx = blockIdx.x * 256 + threadIdx.x;
    if (idx < 2*CH) g_stats[idx] = 0.f;
    if (idx < CH*CH*9) {
        int kc = idx % 3;
        int t  = idx / 3;
        int co = t % CH;
        int t2 = t / CH;
        int kr = t2 % 3;
        int ci = t2 / 3;
        g_wre[idx] = w[((co*CH + ci)*3 + kr)*3 + kc];
    }
}

// ---------------------------------------------------------------------------
// Prep 2: compose curvature filters.
//   cc = linear_conv(fx,fx) + linear_conv(fy,fy)  (5x5), stored flipped so the
//   curvature kernel can use a sliding-window correlation form.
// ---------------------------------------------------------------------------
__global__ void prep_filters(const float* __restrict__ fx, const float* __restrict__ fy) {
    int t = threadIdx.x;
    if (t < 25) {
        int u = t / 5, v = t - 5*(t/5);
        float s = 0.f;
        for (int a = 0; a < 3; a++)
            for (int b = 0; b < 3; b++) {
                int a2 = u - a, b2 = v - b;
                if (a2 >= 0 && a2 < 3 && b2 >= 0 && b2 < 3)
                    s += fx[a*3+b]*fx[a2*3+b2] + fy[a*3+b]*fy[a2*3+b2];
            }
        g_ccF[24 - t] = s;
    } else if (t < 34) {
        int i = t - 25;
        g_fxF[8 - i] = fx[i];
        g_fyF[8 - i] = fy[i];
    }
}

// ---------------------------------------------------------------------------
// Conv 3x3 (pad 1) + bias, fused per-channel sum/sumsq reduction.
// Block: 256 threads, tile 64(W) x 32(H), 4 output channels (one co-group).
// Thread: 8 consecutive W pixels x 4 co.  Weights for the co-group cached in
// smem once; x tile (66x34, stride-67 for conflict-free LDS) reloaded per ci.
// ---------------------------------------------------------------------------
__global__ __launch_bounds__(256) void conv_kernel(
    const float* __restrict__ xin, const float* __restrict__ bias)
{
    __shared__ float s_tile[34*67];
    __shared__ float s_w[64*36];

    int tid = threadIdx.x;
    int bz  = blockIdx.z;
    int cg  = bz & 15;       // co group (4 channels)
    int b   = bz >> 4;       // batch
    int tileW0 = blockIdx.x << 6;
    int tileH0 = blockIdx.y << 5;
    int h0 = tileH0 - 1, w0 = tileW0 - 1;

    // preload this co-group's weights: s_w[ci*36 + kr*12 + co*3 + kc]
    for (int idx = tid; idx < 64*36; idx += 256) {
        int ci  = idx / 36;
        int rem = idx - ci*36;
        int kr  = rem / 12;
        int r2  = rem - kr*12;
        s_w[idx] = g_wre[(ci*3 + kr)*192 + cg*12 + r2];
    }

    int row  = tid >> 3;          // 0..31
    int colg = (tid & 7) << 3;    // 0,8,..,56

    float acc[4][8];
    #pragma unroll
    for (int co = 0; co < 4; co++)
        #pragma unroll
        for (int p = 0; p < 8; p++) acc[co][p] = 0.f;

    const float* xb = xin + (size_t)b * (CH*NPIX);

    for (int ci = 0; ci < 64; ci++) {
        const float* src = xb + ci*NPIX;
        __syncthreads();   // protects s_tile reuse (and s_w on first iter)
        for (int idx = tid; idx < 34*66; idx += 256) {
            int r  = idx / 66;
            int c2 = idx - r*66;
            int gh = h0 + r, gw = w0 + c2;
            float v = 0.f;
            if ((unsigned)gh < 256u && (unsigned)gw < 256u)
                v = src[(gh << 8) + gw];
            s_tile[r*67 + c2] = v;
        }
        __syncthreads();

        const float* wci = &s_w[ci*36];
        #pragma unroll
        for (int kr = 0; kr < 3; kr++) {
            const float* xr = &s_tile[(row + kr)*67 + colg];
            float xv[10];
            #pragma unroll
            for (int j = 0; j < 10; j++) xv[j] = xr[j];
            #pragma unroll
            for (int co = 0; co < 4; co++) {
                float wa = wci[kr*12 + co*3 + 0];
                float wb = wci[kr*12 + co*3 + 1];
                float wc = wci[kr*12 + co*3 + 2];
                #pragma unroll
                for (int p = 0; p < 8; p++)
                    acc[co][p] += wa*xv[p] + wb*xv[p+1] + wc*xv[p+2];
            }
        }
    }

    // epilogue: bias, store y, per-channel partial sums
    int gh   = tileH0 + row;
    int lane = tid & 31;
    int co0  = cg << 2;
    float red[8];
    #pragma unroll
    for (int co = 0; co < 4; co++) {
        float bv = bias[co0 + co];
        float s = 0.f, q = 0.f;
        float vv[8];
        #pragma unroll
        for (int p = 0; p < 8; p++) {
            float v = acc[co][p] + bv;
            vv[p] = v; s += v; q += v*v;
        }
        float* dst = &g_y[(((b << 6) + co0 + co) << 16) + (gh << 8) + tileW0 + colg];
        ((float4*)dst)[0] = make_float4(vv[0], vv[1], vv[2], vv[3]);
        ((float4*)dst)[1] = make_float4(vv[4], vv[5], vv[6], vv[7]);
        red[co*2] = s; red[co*2+1] = q;
    }
    #pragma unroll
    for (int o = 16; o > 0; o >>= 1)
        #pragma unroll
        for (int k = 0; k < 8; k++)
            red[k] += __shfl_xor_sync(0xffffffffu, red[k], o);
    if (lane == 0) {
        #pragma unroll
        for (int co = 0; co < 4; co++) {
            atomicAdd(&g_stats[co0 + co],      red[co*2]);
            atomicAdd(&g_stats[64 + co0 + co], red[co*2+1]);
        }
    }
}

// ---------------------------------------------------------------------------
// Fused BN(batch stats) + ReLU + circular-conv curvature.
//   x   = relu(bn(y))
//   out = circconv5(x, cc) + (circconv3(x,fx) - circconv3(x,fy))^2 + x
// Block: 256 threads, tile 64(W) x 16(H), one (b,c). Thread: 4 px in a row.
// Smem tile 20x68 (4-wide circular halo, stride 69).
// ---------------------------------------------------------------------------
__global__ __launch_bounds__(256) void curv_kernel(
    const float* __restrict__ gamma, const float* __restrict__ beta,
    float* __restrict__ out)
{
    __shared__ float tile[20*69];
    int tid = threadIdx.x;
    int bz  = blockIdx.z;            // b*64 + c
    int c   = bz & 63;
    int h0  = blockIdx.y << 4;
    int w0  = blockIdx.x << 6;

    const float inv_n = 1.f / 524288.f;
    float mean  = g_stats[c] * inv_n;
    float var   = g_stats[64 + c] * inv_n - mean*mean;
    float scale = gamma[c] * rsqrtf(var + 1e-5f);
    float shift = beta[c] - mean*scale;

    const float* yc = g_y + ((size_t)bz << 16);
    for (int idx = tid; idx < 20*68; idx += 256) {
        int r  = idx / 68;
        int c2 = idx - r*68;
        int gh = (h0 + r - 4) & 255;
        int gw = (w0 + c2 - 4) & 255;
        float v = fmaf(yc[(gh << 8) + gw], scale, shift);
        tile[r*69 + c2] = fmaxf(v, 0.f);
    }

    float ccf[25], fxf[9], fyf[9];
    #pragma unroll
    for (int i = 0; i < 25; i++) ccf[i] = g_ccF[i];
    #pragma unroll
    for (int i = 0; i < 9; i++) { fxf[i] = g_fxF[i]; fyf[i] = g_fyF[i]; }
    __syncthreads();

    int tr = tid >> 4;            // 0..15
    int tc = (tid & 15) << 2;     // 0,4,..,60

    float s5[4] = {0,0,0,0};
    float gx[4] = {0,0,0,0};
    float gy[4] = {0,0,0,0};
    float xc[4] = {0,0,0,0};

    #pragma unroll
    for (int r = 0; r < 5; r++) {
        float xv[8];
        const float* rp = &tile[(tr + r)*69 + tc];
        #pragma unroll
        for (int j = 0; j < 8; j++) xv[j] = rp[j];
        #pragma unroll
        for (int u = 0; u < 5; u++) {
            float wv = ccf[r*5 + u];
            #pragma unroll
            for (int p = 0; p < 4; p++) s5[p] = fmaf(wv, xv[p+u], s5[p]);
        }
        if (r >= 2) {
            int r2 = r - 2;
            #pragma unroll
            for (int u2 = 0; u2 < 3; u2++) {
                float wx = fxf[r2*3 + u2];
                float wy = fyf[r2*3 + u2];
                #pragma unroll
                for (int p = 0; p < 4; p++) {
                    gx[p] = fmaf(wx, xv[p+u2+2], gx[p]);
                    gy[p] = fmaf(wy, xv[p+u2+2], gy[p]);
                }
            }
        }
        if (r == 4) {
            #pragma unroll
            for (int p = 0; p < 4; p++) xc[p] = xv[p+4];
        }
    }

    float4 o;
    float d0 = gx[0]-gy[0], d1 = gx[1]-gy[1], d2 = gx[2]-gy[2], d3 = gx[3]-gy[3];
    o.x = s5[0] + d0*d0 + xc[0];
    o.y = s5[1] + d1*d1 + xc[1];
    o.z = s5[2] + d2*d2 + xc[2];
    o.w = s5[3] + d3*d3 + xc[3];
    float* dst = &out[((size_t)bz << 16) + ((h0 + tr) << 8) + w0 + tc];
    *(float4*)dst = o;
}

// ---------------------------------------------------------------------------
extern "C" void kernel_launch(void* const* d_in, const int* in_sizes, int n_in,
                              void* d_out, int out_size)
{
    const float* feature_map = (const float*)d_in[0];
    const float* conv_w      = (const float*)d_in[1];
    const float* conv_b      = (const float*)d_in[2];
    const float* bn_gamma    = (const float*)d_in[3];
    const float* bn_beta     = (const float*)d_in[4];
    const float* filt_x      = (const float*)d_in[5];
    const float* filt_y      = (const float*)d_in[6];
    float* out = (float*)d_out;

    prep_reorder<<<144, 256>>>(conv_w);
    prep_filters<<<1, 64>>>(filt_x, filt_y);
    conv_kernel<<<dim3(4, 8, 128), 256>>>(feature_map, conv_b);
    curv_kernel<<<dim3(4, 16, 512), 256>>>(bn_gamma, bn_beta, out);
}

// round 13
// speedup vs baseline: 1.0067x; 1.0020x over previous
#include <cuda_runtime.h>

#define HH 256
#define WW 256
#define BATCH 8
#define CH 64
#define NPIX 65536
#define NTOT (BATCH*CH*NPIX)

// Scratch (static __device__ arrays per harness rules)
__device__ float g_y[NTOT];              // conv output (pre-BN), 128 MB
__device__ float g_wre[CH*3*CH*3];       // reordered weights [ci][kr][co][kc]
__device__ float g_stats[2*CH];          // per-channel sum, sumsq
__device__ float g_ccF[25];              // flipped composed 5x5 (fx*fx + fy*fy)
__device__ float g_fxF[9];               // flipped 3x3 filters
__device__ float g_fyF[9];

// ---------------------------------------------------------------------------
// Prep 1: reorder conv weights OIHW -> [ci][kr][co][kc], zero stats
// ---------------------------------------------------------------------------
__global__ void prep_reorder(const float* __restrict__ w) {
    int idx = blockIdx.x * 256 + threadIdx.x;
    if (idx < 2*CH) g_stats[idx] = 0.f;
    if (idx < CH*CH*9) {
        int kc = idx % 3;
        int t  = idx / 3;
        int co = t % CH;
        int t2 = t / CH;
        int kr = t2 % 3;
        int ci = t2 / 3;
        g_wre[idx] = w[((co*CH + ci)*3 + kr)*3 + kc];
    }
}

// ---------------------------------------------------------------------------
// Prep 2: compose curvature filters.
//   cc = linear_conv(fx,fx) + linear_conv(fy,fy)  (5x5), stored flipped so the
//   curvature kernel can use a sliding-window correlation form.
// ---------------------------------------------------------------------------
__global__ void prep_filters(const float* __restrict__ fx, const float* __restrict__ fy) {
    int t = threadIdx.x;
    if (t < 25) {
        int u = t / 5, v = t - 5*(t/5);
        float s = 0.f;
        for (int a = 0; a < 3; a++)
            for (int b = 0; b < 3; b++) {
                int a2 = u - a, b2 = v - b;
                if (a2 >= 0 && a2 < 3 && b2 >= 0 && b2 < 3)
                    s += fx[a*3+b]*fx[a2*3+b2] + fy[a*3+b]*fy[a2*3+b2];
            }
        g_ccF[24 - t] = s;
    } else if (t < 34) {
        int i = t - 25;
        g_fxF[8 - i] = fx[i];
        g_fyF[8 - i] = fy[i];
    }
}

// ---------------------------------------------------------------------------
// Conv 3x3 (pad 1) + bias, fused per-channel sum/sumsq reduction.
// Block: 256 threads, tile 64(W) x 32(H), 4 output channels (one co-group).
// Thread: 8 consecutive W pixels x 4 co.  Weights for the co-group cached in
// smem once; x tile (66x34, stride-67 for conflict-free LDS) reloaded per ci.
// ---------------------------------------------------------------------------
__global__ __launch_bounds__(256) void conv_kernel(
    const float* __restrict__ xin, const float* __restrict__ bias)
{
    __shared__ float s_tile[34*67];
    __shared__ float s_w[64*36];

    int tid = threadIdx.x;
    int bz  = blockIdx.z;
    int cg  = bz & 15;       // co group (4 channels)
    int b   = bz >> 4;       // batch
    int tileW0 = blockIdx.x << 6;
    int tileH0 = blockIdx.y << 5;
    int h0 = tileH0 - 1, w0 = tileW0 - 1;

    // preload this co-group's weights: s_w[ci*36 + kr*12 + co*3 + kc]
    for (int idx = tid; idx < 64*36; idx += 256) {
        int ci  = idx / 36;
        int rem = idx - ci*36;
        int kr  = rem / 12;
        int r2  = rem - kr*12;
        s_w[idx] = g_wre[(ci*3 + kr)*192 + cg*12 + r2];
    }

    int row  = tid >> 3;          // 0..31
    int colg = (tid & 7) << 3;    // 0,8,..,56

    float acc[4][8];
    #pragma unroll
    for (int co = 0; co < 4; co++)
        #pragma unroll
        for (int p = 0; p < 8; p++) acc[co][p] = 0.f;

    const float* xb = xin + (size_t)b * (CH*NPIX);

    for (int ci = 0; ci < 64; ci++) {
        const float* src = xb + ci*NPIX;
        __syncthreads();   // protects s_tile reuse (and s_w on first iter)
        for (int idx = tid; idx < 34*66; idx += 256) {
            int r  = idx / 66;
            int c2 = idx - r*66;
            int gh = h0 + r, gw = w0 + c2;
            float v = 0.f;
            if ((unsigned)gh < 256u && (unsigned)gw < 256u)
                v = src[(gh << 8) + gw];
            s_tile[r*67 + c2] = v;
        }
        __syncthreads();

        const float* wci = &s_w[ci*36];
        #pragma unroll
        for (int kr = 0; kr < 3; kr++) {
            const float* xr = &s_tile[(row + kr)*67 + colg];
            float xv[10];
            #pragma unroll
            for (int j = 0; j < 10; j++) xv[j] = xr[j];
            #pragma unroll
            for (int co = 0; co < 4; co++) {
                float wa = wci[kr*12 + co*3 + 0];
                float wb = wci[kr*12 + co*3 + 1];
                float wc = wci[kr*12 + co*3 + 2];
                #pragma unroll
                for (int p = 0; p < 8; p++)
                    acc[co][p] += wa*xv[p] + wb*xv[p+1] + wc*xv[p+2];
            }
        }
    }

    // epilogue: bias, store y, per-channel partial sums
    int gh   = tileH0 + row;
    int lane = tid & 31;
    int co0  = cg << 2;
    float red[8];
    #pragma unroll
    for (int co = 0; co < 4; co++) {
        float bv = bias[co0 + co];
        float s = 0.f, q = 0.f;
        float vv[8];
        #pragma unroll
        for (int p = 0; p < 8; p++) {
            float v = acc[co][p] + bv;
            vv[p] = v; s += v; q += v*v;
        }
        float* dst = &g_y[(((b << 6) + co0 + co) << 16) + (gh << 8) + tileW0 + colg];
        ((float4*)dst)[0] = make_float4(vv[0], vv[1], vv[2], vv[3]);
        ((float4*)dst)[1] = make_float4(vv[4], vv[5], vv[6], vv[7]);
        red[co*2] = s; red[co*2+1] = q;
    }
    #pragma unroll
    for (int o = 16; o > 0; o >>= 1)
        #pragma unroll
        for (int k = 0; k < 8; k++)
            red[k] += __shfl_xor_sync(0xffffffffu, red[k], o);
    if (lane == 0) {
        #pragma unroll
        for (int co = 0; co < 4; co++) {
            atomicAdd(&g_stats[co0 + co],      red[co*2]);
            atomicAdd(&g_stats[64 + co0 + co], red[co*2+1]);
        }
    }
}

// ---------------------------------------------------------------------------
// Fused BN(batch stats) + ReLU + circular-conv curvature.
//   x   = relu(bn(y))
//   out = circconv5(x, cc) + (circconv3(x,fx) - circconv3(x,fy))^2 + x
// Block: 256 threads, tile 64(W) x 16(H), one (b,c). Thread: 4 px in a row.
// Smem tile 20x68 (4-wide circular halo, stride 69).
// ---------------------------------------------------------------------------
__global__ __launch_bounds__(256) void curv_kernel(
    const float* __restrict__ gamma, const float* __restrict__ beta,
    float* __restrict__ out)
{
    __shared__ float tile[20*69];
    int tid = threadIdx.x;
    int bz  = blockIdx.z;            // b*64 + c
    int c   = bz & 63;
    int h0  = blockIdx.y << 4;
    int w0  = blockIdx.x << 6;

    const float inv_n = 1.f / 524288.f;
    float mean  = g_stats[c] * inv_n;
    float var   = g_stats[64 + c] * inv_n - mean*mean;
    float scale = gamma[c] * rsqrtf(var + 1e-5f);
    float shift = beta[c] - mean*scale;

    const float* yc = g_y + ((size_t)bz << 16);
    for (int idx = tid; idx < 20*68; idx += 256) {
        int r  = idx / 68;
        int c2 = idx - r*68;
        int gh = (h0 + r - 4) & 255;
        int gw = (w0 + c2 - 4) & 255;
        float v = fmaf(yc[(gh << 8) + gw], scale, shift);
        tile[r*69 + c2] = fmaxf(v, 0.f);
    }

    float ccf[25], fxf[9], fyf[9];
    #pragma unroll
    for (int i = 0; i < 25; i++) ccf[i] = g_ccF[i];
    #pragma unroll
    for (int i = 0; i < 9; i++) { fxf[i] = g_fxF[i]; fyf[i] = g_fyF[i]; }
    __syncthreads();

    int tr = tid >> 4;            // 0..15
    int tc = (tid & 15) << 2;     // 0,4,..,60

    float s5[4] = {0,0,0,0};
    float gx[4] = {0,0,0,0};
    float gy[4] = {0,0,0,0};
    float xc[4] = {0,0,0,0};

    #pragma unroll
    for (int r = 0; r < 5; r++) {
        float xv[8];
        const float* rp = &tile[(tr + r)*69 + tc];
        #pragma unroll
        for (int j = 0; j < 8; j++) xv[j] = rp[j];
        #pragma unroll
        for (int u = 0; u < 5; u++) {
            float wv = ccf[r*5 + u];
            #pragma unroll
            for (int p = 0; p < 4; p++) s5[p] = fmaf(wv, xv[p+u], s5[p]);
        }
        if (r >= 2) {
            int r2 = r - 2;
            #pragma unroll
            for (int u2 = 0; u2 < 3; u2++) {
                float wx = fxf[r2*3 + u2];
                float wy = fyf[r2*3 + u2];
                #pragma unroll
                for (int p = 0; p < 4; p++) {
                    gx[p] = fmaf(wx, xv[p+u2+2], gx[p]);
                    gy[p] = fmaf(wy, xv[p+u2+2], gy[p]);
                }
            }
        }
        if (r == 4) {
            #pragma unroll
            for (int p = 0; p < 4; p++) xc[p] = xv[p+4];
        }
    }

    float4 o;
    float d0 = gx[0]-gy[0], d1 = gx[1]-gy[1], d2 = gx[2]-gy[2], d3 = gx[3]-gy[3];
    o.x = s5[0] + d0*d0 + xc[0];
    o.y = s5[1] + d1*d1 + xc[1];
    o.z = s5[2] + d2*d2 + xc[2];
    o.w = s5[3] + d3*d3 + xc[3];
    float* dst = &out[((size_t)bz << 16) + ((h0 + tr) << 8) + w0 + tc];
    *(float4*)dst = o;
}

// ---------------------------------------------------------------------------
extern "C" void kernel_launch(void* const* d_in, const int* in_sizes, int n_in,
                              void* d_out, int out_size)
{
    const float* feature_map = (const float*)d_in[0];
    const float* conv_w      = (const float*)d_in[1];
    const float* conv_b      = (const float*)d_in[2];
    const float* bn_gamma    = (const float*)d_in[3];
    const float* bn_beta     = (const float*)d_in[4];
    const float* filt_x      = (const float*)d_in[5];
    const float* filt_y      = (const float*)d_in[6];
    float* out = (float*)d_out;

    prep_reorder<<<144, 256>>>(conv_w);
    prep_filters<<<1, 64>>>(filt_x, filt_y);
    conv_kernel<<<dim3(4, 8, 128), 256>>>(feature_map, conv_b);
    curv_kernel<<<dim3(4, 16, 512), 256>>>(bn_gamma, bn_beta, out);
}